// round 10
// baseline (speedup 1.0000x reference)
#include <cuda_runtime.h>
#include <cuda_bf16.h>
#include <cstdint>

#define SEQ     512
#define INP     5
#define HID     64
#define NB      56          // batch cols per CTA
#define NTL     7           // n-tiles (8 cols each)
#define KT16    4           // full k16 tiles (k=0..63)
#define BPAD    88          // bf16 per B column (44 words = 12 mod 32: conflict-free)
#define THREADS 256

struct SmemT {
    __align__(16) __nv_bfloat16 B[2][2][NB * BPAD];  // [parity][0=hi,1=lo][col][k]
};

__device__ __forceinline__ uint32_t pack_bf16(float lo, float hi) {
    __nv_bfloat162 t = __floats2bfloat162_rn(lo, hi);   // .x=lo (lower 16 bits)
    return *(uint32_t*)&t;
}
__device__ __forceinline__ void split2(float v, float& hi, float& lo) {
    hi = __bfloat162float(__float2bfloat16(v));
    lo = v - hi;
}

// Hardware tanh (sm_75+): 1 MUFU op, max err ~1e-4 abs
__device__ __forceinline__ float tanh_hw(float x) {
    float y;
    asm("tanh.approx.f32 %0, %1;" : "=f"(y) : "f"(x));
    return y;
}
__device__ __forceinline__ float sigmoid_f(float x) {
    return fmaf(tanh_hw(0.5f * x), 0.5f, 0.5f);
}
__device__ __forceinline__ float tanh_f(float x) { return tanh_hw(x); }

// mma.sync m16n8k16 row.col bf16 -> f32, D += A*B
__device__ __forceinline__ void mma16816(float* c, const uint32_t* a, const uint32_t* b) {
    asm volatile(
        "mma.sync.aligned.m16n8k16.row.col.f32.bf16.bf16.f32 "
        "{%0,%1,%2,%3}, {%4,%5,%6,%7}, {%8,%9}, {%0,%1,%2,%3};"
        : "+f"(c[0]), "+f"(c[1]), "+f"(c[2]), "+f"(c[3])
        : "r"(a[0]), "r"(a[1]), "r"(a[2]), "r"(a[3]), "r"(b[0]), "r"(b[1]));
}
// mma.sync m16n8k8 row.col bf16 -> f32, D += A*B (K-tail tile)
__device__ __forceinline__ void mma1688(float* c, const uint32_t* a, uint32_t b) {
    asm volatile(
        "mma.sync.aligned.m16n8k8.row.col.f32.bf16.bf16.f32 "
        "{%0,%1,%2,%3}, {%4,%5}, {%6}, {%0,%1,%2,%3};"
        : "+f"(c[0]), "+f"(c[1]), "+f"(c[2]), "+f"(c[3])
        : "r"(a[0]), "r"(a[1]), "r"(b));
}

// Extended weight matrix element: W_ext[m][k], m permuted so that within a
// warp's m-pair (tiles 2w, 2w+1) each thread's 4 C rows = i,f,g,o of one j.
//   j = (m>>5)*8 + (m&7),  g = 2*((m>>4)&1) + ((m>>3)&1)
__device__ float wext(const float* W_hh, const float* W_ih,
                      const float* b_ih, const float* b_hh, int m, int k) {
    int j   = ((m >> 5) << 3) | (m & 7);
    int g   = (((m >> 4) & 1) << 1) | ((m >> 3) & 1);
    int row = g * HID + j;
    if (k < HID)            return W_hh[row * HID + k];
    if (k < HID + INP)      return W_ih[row * INP + (k - HID)];
    if (k == HID + INP)     return b_ih[row] + b_hh[row];   // bias column
    return 0.f;
}

// ---------------------------------------------------------------------------
// HMMA LSTM (verified R9 structure). Single delta vs R9: n-tiles processed in
// PAIRS with the MMA issue round-robined across 4 independent accumulator
// chains per warp (was 2). Same-chain HMMAs are now ~32 pipe-cycles apart
// (>= accumulator dep latency), removing the dependency stalls that held the
// tensor pipe at 74%.
// ---------------------------------------------------------------------------
__global__ void __launch_bounds__(THREADS, 1)
lstm_hmma_kernel(const float* __restrict__ inputs,  // [B, SEQ, INP]
                 const float* __restrict__ W_ih,    // [256, INP]
                 const float* __restrict__ W_hh,    // [256, HID]
                 const float* __restrict__ b_ih,    // [256]
                 const float* __restrict__ b_hh,    // [256]
                 const float* __restrict__ fc_w,    // [1, HID]
                 const float* __restrict__ fc_b,    // [1]
                 float* __restrict__ out,           // [B, 1]
                 int batch)
{
    __shared__ SmemT sm;

    const int t    = threadIdx.x;
    const int lane = t & 31;
    const int w    = t >> 5;
    const int gid  = lane >> 2;          // fragment row group 0..7
    const int tig  = lane & 3;           // fragment col group 0..3
    const int jm   = (w << 3) | gid;     // this thread's hidden index
    const int batch0 = blockIdx.x * NB;

    // ---- init smem: zero all buffers, set bias row (k=69) = 1.0 in hi bufs
    for (int idx = t; idx < 2 * 2 * NB * BPAD / 2; idx += THREADS)
        ((uint32_t*)sm.B)[idx] = 0u;
    __syncthreads();
    if (t < NB) {
        sm.B[0][0][t * BPAD + HID + INP] = __float2bfloat16(1.0f);
        sm.B[1][0][t * BPAD + HID + INP] = __float2bfloat16(1.0f);
    }

    // x(0) into parity-0 buffer rows 64..68
    for (int q = t; q < NB * INP; q += THREADS) {
        int col = q / INP, i = q - col * INP;
        int row = min(batch0 + col, batch - 1);
        float xv = inputs[(size_t)row * (SEQ * INP) + i];
        float xh, xl; split2(xv, xh, xl);
        sm.B[0][0][col * BPAD + HID + i] = __float2bfloat16(xh);
        sm.B[0][1][col * BPAD + HID + i] = __float2bfloat16(xl);
    }

    // ---- load W_ext fragments into registers (hi/lo), one-time
    uint32_t ahi[2][KT16][4], alo[2][KT16][4];   // k16 tiles, k=0..63
    uint32_t ahi8[2][2], alo8[2][2];             // k8 tail, k=64..71
#pragma unroll
    for (int mt = 0; mt < 2; ++mt) {
        const int mbase = ((w << 1) | mt) << 4;
#pragma unroll
        for (int kt = 0; kt < KT16; ++kt) {
#pragma unroll
            for (int cp = 0; cp < 2; ++cp) {          // col pair: k+0/1 or k+8/9
#pragma unroll
                for (int rr = 0; rr < 2; ++rr) {      // row gid or gid+8
                    int m  = mbase + gid + rr * 8;
                    int k0 = kt * 16 + 2 * tig + cp * 8;
                    float v0 = wext(W_hh, W_ih, b_ih, b_hh, m, k0);
                    float v1 = wext(W_hh, W_ih, b_ih, b_hh, m, k0 + 1);
                    float h0, l0, h1, l1;
                    split2(v0, h0, l0);
                    split2(v1, h1, l1);
                    ahi[mt][kt][cp * 2 + rr] = pack_bf16(h0, h1);
                    alo[mt][kt][cp * 2 + rr] = pack_bf16(l0, l1);
                }
            }
        }
        // k8 tail: k = 64 + 2*tig (+1)
#pragma unroll
        for (int rr = 0; rr < 2; ++rr) {
            int m  = mbase + gid + rr * 8;
            int k0 = 64 + 2 * tig;
            float v0 = wext(W_hh, W_ih, b_ih, b_hh, m, k0);
            float v1 = wext(W_hh, W_ih, b_ih, b_hh, m, k0 + 1);
            float h0, l0, h1, l1;
            split2(v0, h0, l0);
            split2(v1, h1, l1);
            ahi8[mt][rr] = pack_bf16(h0, h1);
            alo8[mt][rr] = pack_bf16(l0, l1);
        }
    }

    // x prefetch ownership: indices t and t+256 (< NB*INP = 280)
    const int  q1   = t + THREADS;
    const bool hq1  = q1 < NB * INP;
    const int  c0i  = t / INP,  i0 = t - c0i * INP;
    const int  c1i  = hq1 ? q1 / INP : 0, i1 = hq1 ? q1 - c1i * INP : 0;
    const float* xp0 = inputs + (size_t)min(batch0 + c0i, batch - 1) * (SEQ * INP) + i0;
    const float* xp1 = inputs + (size_t)min(batch0 + c1i, batch - 1) * (SEQ * INP) + i1;

    float cst[2 * NTL];
#pragma unroll
    for (int q = 0; q < 2 * NTL; ++q) cst[q] = 0.f;

    __syncthreads();

    for (int s = 0; s < SEQ; ++s) {
        // prefetch next x
        float xv0 = 0.f, xv1 = 0.f;
        const bool dox = (s + 1 < SEQ);
        if (dox) {
            xv0 = __ldg(xp0 + (size_t)(s + 1) * INP);
            if (hq1) xv1 = __ldg(xp1 + (size_t)(s + 1) * INP);
        }

        const __nv_bfloat16* BH = sm.B[s & 1][0];
        const __nv_bfloat16* BL = sm.B[s & 1][1];
        __nv_bfloat16* WH = sm.B[(s + 1) & 1][0];
        __nv_bfloat16* WL = sm.B[(s + 1) & 1][1];

        float cacc[2][NTL][4];

        // B fragments for the two tiles of the current pair
        uint32_t bh[2][KT16][2], bl[2][KT16][2], b8h[2], b8l[2];

#define LOADFRAG(buf, nt)                                                     \
        {                                                                     \
            const int ncol = (nt) * 8 + gid;                                  \
            const uint32_t* colH = (const uint32_t*)(BH + ncol * BPAD);       \
            const uint32_t* colL = (const uint32_t*)(BL + ncol * BPAD);       \
            _Pragma("unroll")                                                 \
            for (int kt = 0; kt < KT16; ++kt) {                               \
                bh[buf][kt][0] = colH[kt * 8 + tig];                          \
                bh[buf][kt][1] = colH[kt * 8 + tig + 4];                      \
                bl[buf][kt][0] = colL[kt * 8 + tig];                          \
                bl[buf][kt][1] = colL[kt * 8 + tig + 4];                      \
            }                                                                 \
            b8h[buf] = colH[32 + tig];                                        \
            b8l[buf] = colL[32 + tig];                                        \
        }

        // Epilogue for one n-tile: cells (j=jm, col = nt*8 + 2tig + q)
#define EPILOGUE(nt)                                                          \
        {                                                                     \
            _Pragma("unroll")                                                 \
            for (int q = 0; q < 2; ++q) {                                     \
                const float gi = cacc[0][nt][q];                              \
                const float gf = cacc[0][nt][2 + q];                          \
                const float gg = cacc[1][nt][q];                              \
                const float go = cacc[1][nt][2 + q];                          \
                const float ig = sigmoid_f(gi);                               \
                const float fg = sigmoid_f(gf);                               \
                const float gt = tanh_f(gg);                                  \
                const float og = sigmoid_f(go);                               \
                const int  ci = (nt) * 2 + q;                                 \
                const float cn = fg * cst[ci] + ig * gt;                      \
                cst[ci] = cn;                                                 \
                const float hv = og * tanh_f(cn);                             \
                float hh, hl; split2(hv, hh, hl);                             \
                const int col = (nt) * 8 + 2 * tig + q;                       \
                WH[col * BPAD + jm] = __float2bfloat16(hh);                   \
                WL[col * BPAD + jm] = __float2bfloat16(hl);                   \
            }                                                                 \
        }

        // ---- pairs (0,1), (2,3), (4,5): 4 independent MMA chains each ----
#pragma unroll
        for (int np = 0; np < 3; ++np) {
            const int n0 = 2 * np, n1 = n0 + 1;
            LOADFRAG(0, n0);
            LOADFRAG(1, n1);
#pragma unroll
            for (int q = 0; q < 4; ++q) {
                cacc[0][n0][q] = 0.f; cacc[1][n0][q] = 0.f;
                cacc[0][n1][q] = 0.f; cacc[1][n1][q] = 0.f;
            }
            // round-robin across 4 chains: same-chain gap = 4 issues (~32 pipe cyc)
#pragma unroll
            for (int kt = 0; kt < KT16; ++kt) {
                mma16816(cacc[0][n0], ahi[0][kt], bh[0][kt]);
                mma16816(cacc[1][n0], ahi[1][kt], bh[0][kt]);
                mma16816(cacc[0][n1], ahi[0][kt], bh[1][kt]);
                mma16816(cacc[1][n1], ahi[1][kt], bh[1][kt]);
                mma16816(cacc[0][n0], ahi[0][kt], bl[0][kt]);
                mma16816(cacc[1][n0], ahi[1][kt], bl[0][kt]);
                mma16816(cacc[0][n1], ahi[0][kt], bl[1][kt]);
                mma16816(cacc[1][n1], ahi[1][kt], bl[1][kt]);
                mma16816(cacc[0][n0], alo[0][kt], bh[0][kt]);
                mma16816(cacc[1][n0], alo[1][kt], bh[0][kt]);
                mma16816(cacc[0][n1], alo[0][kt], bh[1][kt]);
                mma16816(cacc[1][n1], alo[1][kt], bh[1][kt]);
            }
            mma1688(cacc[0][n0], ahi8[0], b8h[0]);
            mma1688(cacc[1][n0], ahi8[1], b8h[0]);
            mma1688(cacc[0][n1], ahi8[0], b8h[1]);
            mma1688(cacc[1][n1], ahi8[1], b8h[1]);
            mma1688(cacc[0][n0], ahi8[0], b8l[0]);
            mma1688(cacc[1][n0], ahi8[1], b8l[0]);
            mma1688(cacc[0][n1], ahi8[0], b8l[1]);
            mma1688(cacc[1][n1], ahi8[1], b8l[1]);
            mma1688(cacc[0][n0], alo8[0], b8h[0]);
            mma1688(cacc[1][n0], alo8[1], b8h[0]);
            mma1688(cacc[0][n1], alo8[0], b8h[1]);
            mma1688(cacc[1][n1], alo8[1], b8h[1]);

            if (np > 0) { EPILOGUE(n0 - 2); EPILOGUE(n0 - 1); }
        }

        // ---- lone tile 6 (2 chains; epilogues of (4,5) fill the gaps) ----
        {
            LOADFRAG(0, 6);
#pragma unroll
            for (int q = 0; q < 4; ++q) { cacc[0][6][q] = 0.f; cacc[1][6][q] = 0.f; }
#pragma unroll
            for (int kt = 0; kt < KT16; ++kt) {
                mma16816(cacc[0][6], ahi[0][kt], bh[0][kt]);
                mma16816(cacc[1][6], ahi[1][kt], bh[0][kt]);
                mma16816(cacc[0][6], ahi[0][kt], bl[0][kt]);
                mma16816(cacc[1][6], ahi[1][kt], bl[0][kt]);
                mma16816(cacc[0][6], alo[0][kt], bh[0][kt]);
                mma16816(cacc[1][6], alo[1][kt], bh[0][kt]);
            }
            mma1688(cacc[0][6], ahi8[0], b8h[0]);
            mma1688(cacc[1][6], ahi8[1], b8h[0]);
            mma1688(cacc[0][6], ahi8[0], b8l[0]);
            mma1688(cacc[1][6], ahi8[1], b8l[0]);
            mma1688(cacc[0][6], alo8[0], b8h[0]);
            mma1688(cacc[1][6], alo8[1], b8h[0]);

            EPILOGUE(4); EPILOGUE(5);
        }
        EPILOGUE(6);
#undef EPILOGUE
#undef LOADFRAG

        // stash next x into next-parity buffer
        if (dox) {
            float xh, xl;
            split2(xv0, xh, xl);
            WH[c0i * BPAD + HID + i0] = __float2bfloat16(xh);
            WL[c0i * BPAD + HID + i0] = __float2bfloat16(xl);
            if (hq1) {
                split2(xv1, xh, xl);
                WH[c1i * BPAD + HID + i1] = __float2bfloat16(xh);
                WL[c1i * BPAD + HID + i1] = __float2bfloat16(xl);
            }
        }
        __syncthreads();
    }

    // ---- final FC + leaky ReLU; h(512) is in parity-0 buffer (hi+lo)
    const __nv_bfloat16* FH = sm.B[0][0];
    const __nv_bfloat16* FL = sm.B[0][1];
    const float fw0 = fc_w[lane], fw1 = fc_w[lane + 32];
    const float fb  = fc_b[0];
#pragma unroll
    for (int q = 0; q < NTL; ++q) {
        const int col = w * NTL + q;
        float hA = __bfloat162float(FH[col * BPAD + lane])
                 + __bfloat162float(FL[col * BPAD + lane]);
        float hB = __bfloat162float(FH[col * BPAD + lane + 32])
                 + __bfloat162float(FL[col * BPAD + lane + 32]);
        float p = hA * fw0 + hB * fw1;
#pragma unroll
        for (int off = 16; off > 0; off >>= 1)
            p += __shfl_xor_sync(0xffffffffu, p, off);
        if (lane == 0) {
            const int row = batch0 + col;
            if (row < batch) {
                const float v = p + fb;
                out[row] = (v >= 0.f) ? v : 0.01f * v;
            }
        }
    }
}

extern "C" void kernel_launch(void* const* d_in, const int* in_sizes, int n_in,
                              void* d_out, int out_size) {
    const float* inputs = (const float*)d_in[0];
    const float* W_ih   = (const float*)d_in[1];
    const float* W_hh   = (const float*)d_in[2];
    const float* b_ih   = (const float*)d_in[3];
    const float* b_hh   = (const float*)d_in[4];
    const float* fc_w   = (const float*)d_in[5];
    const float* fc_b   = (const float*)d_in[6];
    float*       out    = (float*)d_out;

    const int batch = in_sizes[0] / (SEQ * INP);      // 8192
    const int grid  = (batch + NB - 1) / NB;          // 147

    lstm_hmma_kernel<<<grid, THREADS>>>(inputs, W_ih, W_hh, b_ih, b_hh,
                                        fc_w, fc_b, out, batch);
}

// round 11
// speedup vs baseline: 1.0238x; 1.0238x over previous
#include <cuda_runtime.h>
#include <cuda_bf16.h>
#include <cstdint>

#define SEQ     512
#define INP     5
#define HID     64
#define NB      56          // batch cols per CTA
#define NTL     7           // n-tiles (8 cols each)
#define KT16    4           // full k16 tiles (k=0..63)
#define BPAD    88          // bf16 per B column (44 words = 12 mod 32: conflict-free)
#define THREADS 256

struct SmemT {
    __align__(16) __nv_bfloat16 B[2][2][NB * BPAD];  // [parity][0=hi,1=lo][col][k]
};

__device__ __forceinline__ uint32_t pack_bf16(float lo, float hi) {
    __nv_bfloat162 t = __floats2bfloat162_rn(lo, hi);   // .x=lo (lower 16 bits)
    return *(uint32_t*)&t;
}
__device__ __forceinline__ void split2(float v, float& hi, float& lo) {
    hi = __bfloat162float(__float2bfloat16(v));
    lo = v - hi;
}

// Hardware tanh (sm_75+): 1 MUFU op, max err ~1e-4 abs
__device__ __forceinline__ float tanh_hw(float x) {
    float y;
    asm("tanh.approx.f32 %0, %1;" : "=f"(y) : "f"(x));
    return y;
}
__device__ __forceinline__ float sigmoid_f(float x) {
    return fmaf(tanh_hw(0.5f * x), 0.5f, 0.5f);
}
__device__ __forceinline__ float tanh_f(float x) { return tanh_hw(x); }

// mma.sync m16n8k16 row.col bf16 -> f32, D += A*B
__device__ __forceinline__ void mma16816(float* c, const uint32_t* a, const uint32_t* b) {
    asm volatile(
        "mma.sync.aligned.m16n8k16.row.col.f32.bf16.bf16.f32 "
        "{%0,%1,%2,%3}, {%4,%5,%6,%7}, {%8,%9}, {%0,%1,%2,%3};"
        : "+f"(c[0]), "+f"(c[1]), "+f"(c[2]), "+f"(c[3])
        : "r"(a[0]), "r"(a[1]), "r"(a[2]), "r"(a[3]), "r"(b[0]), "r"(b[1]));
}
// mma.sync m16n8k8 row.col bf16 -> f32, D += A*B (K-tail tile)
__device__ __forceinline__ void mma1688(float* c, const uint32_t* a, uint32_t b) {
    asm volatile(
        "mma.sync.aligned.m16n8k8.row.col.f32.bf16.bf16.f32 "
        "{%0,%1,%2,%3}, {%4,%5}, {%6}, {%0,%1,%2,%3};"
        : "+f"(c[0]), "+f"(c[1]), "+f"(c[2]), "+f"(c[3])
        : "r"(a[0]), "r"(a[1]), "r"(b));
}

// Extended weight matrix element: W_ext[m][k], m permuted so that within a
// warp's m-pair (tiles 2w, 2w+1) each thread's 4 C rows = i,f,g,o of one j.
//   j = (m>>5)*8 + (m&7),  g = 2*((m>>4)&1) + ((m>>3)&1)
__device__ float wext(const float* W_hh, const float* W_ih,
                      const float* b_ih, const float* b_hh, int m, int k) {
    int j   = ((m >> 5) << 3) | (m & 7);
    int g   = (((m >> 4) & 1) << 1) | ((m >> 3) & 1);
    int row = g * HID + j;
    if (k < HID)            return W_hh[row * HID + k];
    if (k < HID + INP)      return W_ih[row * INP + (k - HID)];
    if (k == HID + INP)     return b_ih[row] + b_hh[row];   // bias column
    return 0.f;
}

// ---------------------------------------------------------------------------
// HMMA LSTM (verified R9 structure). Single delta vs R9: warps 4-7 (the
// second warp on each SMSP) process the 7 n-tiles in ROTATED order
// (phys = (nt+4) % 7). Tile reads are read-only prev-h and epilogue writes
// are disjoint, so order is free; the rotation structurally decorrelates the
// two co-resident warps' MMA/epilogue phases so one warp's MUFU epilogue
// fills the tensor pipe gaps of the other.
// ---------------------------------------------------------------------------
__global__ void __launch_bounds__(THREADS, 1)
lstm_hmma_kernel(const float* __restrict__ inputs,  // [B, SEQ, INP]
                 const float* __restrict__ W_ih,    // [256, INP]
                 const float* __restrict__ W_hh,    // [256, HID]
                 const float* __restrict__ b_ih,    // [256]
                 const float* __restrict__ b_hh,    // [256]
                 const float* __restrict__ fc_w,    // [1, HID]
                 const float* __restrict__ fc_b,    // [1]
                 float* __restrict__ out,           // [B, 1]
                 int batch)
{
    __shared__ SmemT sm;

    const int t    = threadIdx.x;
    const int lane = t & 31;
    const int w    = t >> 5;
    const int gid  = lane >> 2;          // fragment row group 0..7
    const int tig  = lane & 3;           // fragment col group 0..3
    const int jm   = (w << 3) | gid;     // this thread's hidden index
    const int batch0 = blockIdx.x * NB;

    // Tile-order rotation: SMSP = w%4 hosts warps w and w+4 -> rotate the
    // upper four warps by 4 tiles (~half the step).
    const int rot = ((w >> 2) & 1) * 4;
#define PHYS(nt) ((nt) + rot >= NTL ? (nt) + rot - NTL : (nt) + rot)

    // ---- init smem: zero all buffers, set bias row (k=69) = 1.0 in hi bufs
    for (int idx = t; idx < 2 * 2 * NB * BPAD / 2; idx += THREADS)
        ((uint32_t*)sm.B)[idx] = 0u;
    __syncthreads();
    if (t < NB) {
        sm.B[0][0][t * BPAD + HID + INP] = __float2bfloat16(1.0f);
        sm.B[1][0][t * BPAD + HID + INP] = __float2bfloat16(1.0f);
    }

    // x(0) into parity-0 buffer rows 64..68
    for (int q = t; q < NB * INP; q += THREADS) {
        int col = q / INP, i = q - col * INP;
        int row = min(batch0 + col, batch - 1);
        float xv = inputs[(size_t)row * (SEQ * INP) + i];
        float xh, xl; split2(xv, xh, xl);
        sm.B[0][0][col * BPAD + HID + i] = __float2bfloat16(xh);
        sm.B[0][1][col * BPAD + HID + i] = __float2bfloat16(xl);
    }

    // ---- load W_ext fragments into registers (hi/lo), one-time
    uint32_t ahi[2][KT16][4], alo[2][KT16][4];   // k16 tiles, k=0..63
    uint32_t ahi8[2][2], alo8[2][2];             // k8 tail, k=64..71
#pragma unroll
    for (int mt = 0; mt < 2; ++mt) {
        const int mbase = ((w << 1) | mt) << 4;
#pragma unroll
        for (int kt = 0; kt < KT16; ++kt) {
#pragma unroll
            for (int cp = 0; cp < 2; ++cp) {          // col pair: k+0/1 or k+8/9
#pragma unroll
                for (int rr = 0; rr < 2; ++rr) {      // row gid or gid+8
                    int m  = mbase + gid + rr * 8;
                    int k0 = kt * 16 + 2 * tig + cp * 8;
                    float v0 = wext(W_hh, W_ih, b_ih, b_hh, m, k0);
                    float v1 = wext(W_hh, W_ih, b_ih, b_hh, m, k0 + 1);
                    float h0, l0, h1, l1;
                    split2(v0, h0, l0);
                    split2(v1, h1, l1);
                    ahi[mt][kt][cp * 2 + rr] = pack_bf16(h0, h1);
                    alo[mt][kt][cp * 2 + rr] = pack_bf16(l0, l1);
                }
            }
        }
        // k8 tail: k = 64 + 2*tig (+1)
#pragma unroll
        for (int rr = 0; rr < 2; ++rr) {
            int m  = mbase + gid + rr * 8;
            int k0 = 64 + 2 * tig;
            float v0 = wext(W_hh, W_ih, b_ih, b_hh, m, k0);
            float v1 = wext(W_hh, W_ih, b_ih, b_hh, m, k0 + 1);
            float h0, l0, h1, l1;
            split2(v0, h0, l0);
            split2(v1, h1, l1);
            ahi8[mt][rr] = pack_bf16(h0, h1);
            alo8[mt][rr] = pack_bf16(l0, l1);
        }
    }

    // x prefetch ownership: indices t and t+256 (< NB*INP = 280)
    const int  q1   = t + THREADS;
    const bool hq1  = q1 < NB * INP;
    const int  c0i  = t / INP,  i0 = t - c0i * INP;
    const int  c1i  = hq1 ? q1 / INP : 0, i1 = hq1 ? q1 - c1i * INP : 0;
    const float* xp0 = inputs + (size_t)min(batch0 + c0i, batch - 1) * (SEQ * INP) + i0;
    const float* xp1 = inputs + (size_t)min(batch0 + c1i, batch - 1) * (SEQ * INP) + i1;

    // c state: cst[nt*2+q] is keyed by LOGICAL loop index (mapping to physical
    // cells is fixed per warp by the constant rotation -> consistent across steps)
    float cst[2 * NTL];
#pragma unroll
    for (int q = 0; q < 2 * NTL; ++q) cst[q] = 0.f;

    __syncthreads();

    for (int s = 0; s < SEQ; ++s) {
        // prefetch next x
        float xv0 = 0.f, xv1 = 0.f;
        const bool dox = (s + 1 < SEQ);
        if (dox) {
            xv0 = __ldg(xp0 + (size_t)(s + 1) * INP);
            if (hq1) xv1 = __ldg(xp1 + (size_t)(s + 1) * INP);
        }

        const __nv_bfloat16* BH = sm.B[s & 1][0];
        const __nv_bfloat16* BL = sm.B[s & 1][1];
        __nv_bfloat16* WH = sm.B[(s + 1) & 1][0];
        __nv_bfloat16* WL = sm.B[(s + 1) & 1][1];

        float cacc[2][NTL][4];

        // B fragments, double-buffered across n-tiles
        uint32_t bh[2][KT16][2], bl[2][KT16][2], b8h[2], b8l[2];

        // pnt = physical tile index (rotated); buf/cacc/cst use logical nt
#define LOADFRAG(buf, pnt)                                                    \
        {                                                                     \
            const int ncol = (pnt) * 8 + gid;                                 \
            const uint32_t* colH = (const uint32_t*)(BH + ncol * BPAD);       \
            const uint32_t* colL = (const uint32_t*)(BL + ncol * BPAD);       \
            _Pragma("unroll")                                                 \
            for (int kt = 0; kt < KT16; ++kt) {                               \
                bh[buf][kt][0] = colH[kt * 8 + tig];                          \
                bh[buf][kt][1] = colH[kt * 8 + tig + 4];                      \
                bl[buf][kt][0] = colL[kt * 8 + tig];                          \
                bl[buf][kt][1] = colL[kt * 8 + tig + 4];                      \
            }                                                                 \
            b8h[buf] = colH[32 + tig];                                        \
            b8l[buf] = colL[32 + tig];                                        \
        }

        // Epilogue: logical tile nt (registers), physical tile pnt (smem col)
#define EPILOGUE(nt, pnt)                                                     \
        {                                                                     \
            _Pragma("unroll")                                                 \
            for (int q = 0; q < 2; ++q) {                                     \
                const float gi = cacc[0][nt][q];                              \
                const float gf = cacc[0][nt][2 + q];                          \
                const float gg = cacc[1][nt][q];                              \
                const float go = cacc[1][nt][2 + q];                          \
                const float ig = sigmoid_f(gi);                               \
                const float fg = sigmoid_f(gf);                               \
                const float gt = tanh_f(gg);                                  \
                const float og = sigmoid_f(go);                               \
                const int  ci = (nt) * 2 + q;                                 \
                const float cn = fg * cst[ci] + ig * gt;                      \
                cst[ci] = cn;                                                 \
                const float hv = og * tanh_f(cn);                             \
                float hh, hl; split2(hv, hh, hl);                             \
                const int col = (pnt) * 8 + 2 * tig + q;                      \
                WH[col * BPAD + jm] = __float2bfloat16(hh);                   \
                WL[col * BPAD + jm] = __float2bfloat16(hl);                   \
            }                                                                 \
        }

        LOADFRAG(0, PHYS(0));
#pragma unroll
        for (int nt = 0; nt < NTL; ++nt) {
            const int cur = nt & 1, nxt = cur ^ 1;
            // pipeline: next tile's LDS issue before this tile's MMA burst
            if (nt + 1 < NTL) LOADFRAG(nxt, PHYS(nt + 1));

#pragma unroll
            for (int mt = 0; mt < 2; ++mt)
#pragma unroll
                for (int q = 0; q < 4; ++q) cacc[mt][nt][q] = 0.f;

            // mt-interleaved issue: two independent accumulator chains
#pragma unroll
            for (int kt = 0; kt < KT16; ++kt) {
                mma16816(cacc[0][nt], ahi[0][kt], bh[cur][kt]);
                mma16816(cacc[1][nt], ahi[1][kt], bh[cur][kt]);
                mma16816(cacc[0][nt], ahi[0][kt], bl[cur][kt]);
                mma16816(cacc[1][nt], ahi[1][kt], bl[cur][kt]);
                mma16816(cacc[0][nt], alo[0][kt], bh[cur][kt]);
                mma16816(cacc[1][nt], alo[1][kt], bh[cur][kt]);
            }
            mma1688(cacc[0][nt], ahi8[0], b8h[cur]);
            mma1688(cacc[1][nt], ahi8[1], b8h[cur]);
            mma1688(cacc[0][nt], ahi8[0], b8l[cur]);
            mma1688(cacc[1][nt], ahi8[1], b8l[cur]);
            mma1688(cacc[0][nt], alo8[0], b8h[cur]);
            mma1688(cacc[1][nt], alo8[1], b8h[cur]);

            if (nt > 0) EPILOGUE(nt - 1, PHYS(nt - 1));
        }
        EPILOGUE(NTL - 1, PHYS(NTL - 1));
#undef EPILOGUE
#undef LOADFRAG

        // stash next x into next-parity buffer
        if (dox) {
            float xh, xl;
            split2(xv0, xh, xl);
            WH[c0i * BPAD + HID + i0] = __float2bfloat16(xh);
            WL[c0i * BPAD + HID + i0] = __float2bfloat16(xl);
            if (hq1) {
                split2(xv1, xh, xl);
                WH[c1i * BPAD + HID + i1] = __float2bfloat16(xh);
                WL[c1i * BPAD + HID + i1] = __float2bfloat16(xl);
            }
        }
        __syncthreads();
    }

    // ---- final FC + leaky ReLU; h(512) is in parity-0 buffer (hi+lo)
    const __nv_bfloat16* FH = sm.B[0][0];
    const __nv_bfloat16* FL = sm.B[0][1];
    const float fw0 = fc_w[lane], fw1 = fc_w[lane + 32];
    const float fb  = fc_b[0];
#pragma unroll
    for (int q = 0; q < NTL; ++q) {
        const int col = w * NTL + q;
        float hA = __bfloat162float(FH[col * BPAD + lane])
                 + __bfloat162float(FL[col * BPAD + lane]);
        float hB = __bfloat162float(FH[col * BPAD + lane + 32])
                 + __bfloat162float(FL[col * BPAD + lane + 32]);
        float p = hA * fw0 + hB * fw1;
#pragma unroll
        for (int off = 16; off > 0; off >>= 1)
            p += __shfl_xor_sync(0xffffffffu, p, off);
        if (lane == 0) {
            const int row = batch0 + col;
            if (row < batch) {
                const float v = p + fb;
                out[row] = (v >= 0.f) ? v : 0.01f * v;
            }
        }
    }
#undef PHYS
}

extern "C" void kernel_launch(void* const* d_in, const int* in_sizes, int n_in,
                              void* d_out, int out_size) {
    const float* inputs = (const float*)d_in[0];
    const float* W_ih   = (const float*)d_in[1];
    const float* W_hh   = (const float*)d_in[2];
    const float* b_ih   = (const float*)d_in[3];
    const float* b_hh   = (const float*)d_in[4];
    const float* fc_w   = (const float*)d_in[5];
    const float* fc_b   = (const float*)d_in[6];
    float*       out    = (float*)d_out;

    const int batch = in_sizes[0] / (SEQ * INP);      // 8192
    const int grid  = (batch + NB - 1) / NB;          // 147

    lstm_hmma_kernel<<<grid, THREADS>>>(inputs, W_ih, W_hh, b_ih, b_hh,
                                        fc_w, fc_b, out, batch);
}